// round 14
// baseline (speedup 1.0000x reference)
#include <cuda_runtime.h>
#include <cstdint>

// Depthwise1d: out[n,c,o] = sum_i x[n,c,i] * W[c,o,i] + b[c,o]
// N=4096, C=256, K=64, O=128, fp32.
//
// R13: R6 skeleton (fresh CTA per 128x128 tile, x staged via LDG/STS, W
// pre-transposed k-major, col-pair FFMA2 r=8 x c=8) with an EXPLICIT
// 2-stage software pipeline in the k-loop: stage-B LDS issues before the
// stage-A FFMA2 burst, hiding shared-memory latency at 4 warps/SMSP.

#define N_TOT   4096
#define C_TOT   256
#define K_IN    64
#define O_OUT   128
#define TILE_M  128
#define THREADS 256
#define XSTR    68       // Xsh row stride (floats)
#define WSTR    132      // Wsh k-row stride (floats)

// 8 MB scratch: W2g[c][k][o]
__device__ float W2g[C_TOT * K_IN * O_OUT];

__device__ __forceinline__ void ffma2(unsigned long long& d,
                                      unsigned long long a,
                                      unsigned long long b) {
    asm("fma.rn.f32x2 %0, %1, %2, %0;" : "+l"(d) : "l"(a), "l"(b));
}
__device__ __forceinline__ unsigned long long dup2(float w) {
    unsigned long long r;
    asm("mov.b64 %0, {%1, %1};" : "=l"(r) : "f"(w));
    return r;
}
__device__ __forceinline__ float2 unpack2(unsigned long long v) {
    float2 f;
    asm("mov.b64 {%0, %1}, %2;" : "=f"(f.x), "=f"(f.y) : "l"(v));
    return f;
}

// ---- Kernel A: W[c][o][k] -> W2g[c][k][o] (tiny) ----
__global__ __launch_bounds__(256)
void w_transpose(const float* __restrict__ W) {
    __shared__ float Wt[O_OUT * 68];
    const int t = threadIdx.x;
    const int c = blockIdx.x;
#pragma unroll
    for (int j = 0; j < 8; ++j) {
        int idx = t + 256 * j;
        int o = idx >> 4, q = idx & 15;
        float4 v = *(const float4*)(W + ((size_t)c * O_OUT + o) * K_IN + 4 * q);
        *(float4*)&Wt[o * 68 + 4 * q] = v;
    }
    __syncthreads();
    float* dst = W2g + (size_t)c * K_IN * O_OUT;
#pragma unroll
    for (int j = 0; j < 32; ++j) {
        int idx = t + 256 * j;
        int k = idx >> 7, o = idx & 127;
        dst[k * O_OUT + o] = Wt[o * 68 + k];
    }
}

// one pipeline stage: xs (8 broadcast LDS.32) + W rows (2 LDS.128)
struct Stage {
    float xs[8];
    ulonglong2 wv0, wv1;
};

__device__ __forceinline__ void load_stage(Stage& s,
                                           const float* __restrict__ Xsh,
                                           const float* __restrict__ wrow0,
                                           const float* __restrict__ wrow1,
                                           int k, int rg) {
#pragma unroll
    for (int i = 0; i < 8; ++i)
        s.xs[i] = Xsh[(rg + 16 * i) * XSTR + k];
    s.wv0 = *(const ulonglong2*)(wrow0 + k * WSTR);
    s.wv1 = *(const ulonglong2*)(wrow1 + k * WSTR);
}

__device__ __forceinline__ void fma_stage(unsigned long long (&acc)[8][4],
                                          const Stage& s) {
#pragma unroll
    for (int i = 0; i < 8; ++i) {
        unsigned long long xd = dup2(s.xs[i]);
        ffma2(acc[i][0], xd, s.wv0.x);
        ffma2(acc[i][1], xd, s.wv0.y);
        ffma2(acc[i][2], xd, s.wv1.x);
        ffma2(acc[i][3], xd, s.wv1.y);
    }
}

// ---- Kernel B: main GEMM ----
__global__ __launch_bounds__(THREADS, 2)
void dw1d_kernel(const float* __restrict__ x,
                 const float* __restrict__ b,
                 float* __restrict__ out) {
    extern __shared__ float smem[];
    float* Xsh = smem;                       // [row][k] stride XSTR
    float* Wsh = smem + TILE_M * XSTR;       // [k][o]   stride WSTR

    const int t  = threadIdx.x;
    const int cg = t & 15;
    const int rg = t >> 4;
    const int n0 = blockIdx.x * TILE_M;
    const int c  = blockIdx.y;

    // stage x: coalesced LDG.128 -> Xsh[row][k]
    {
        const float* xb = x + (size_t)c * K_IN;
#pragma unroll
        for (int j = 0; j < 8; ++j) {
            int idx = t + THREADS * j;       // 0..2047
            int row = idx >> 4, ku = idx & 15;
            float4 v = *(const float4*)(xb + (size_t)(n0 + row) * C_TOT * K_IN + 4 * ku);
            *(float4*)&Xsh[row * XSTR + 4 * ku] = v;
        }
    }
    // stage W (k-major): coalesced LDG.128 -> Wsh[k][o]
    {
        const float* wb = W2g + (size_t)c * K_IN * O_OUT;
#pragma unroll
        for (int j = 0; j < 8; ++j) {
            int idx = t + THREADS * j;       // 0..2047
            int k = idx >> 5, o4 = idx & 31;
            float4 v = *(const float4*)(wb + k * O_OUT + 4 * o4);
            *(float4*)&Wsh[k * WSTR + 4 * o4] = v;
        }
    }
    __syncthreads();

    // compute: rows r_i = rg + 16*i (i<8); cols {4cg..+3, 64+4cg..+3}
    unsigned long long acc[8][4];
#pragma unroll
    for (int i = 0; i < 8; ++i)
#pragma unroll
        for (int j = 0; j < 4; ++j)
            acc[i][j] = 0ULL;

    const float* wrow0 = &Wsh[4 * cg];
    const float* wrow1 = &Wsh[4 * cg + 64];

    // 2-stage software pipeline over k
    Stage A, B;
    load_stage(A, Xsh, wrow0, wrow1, 0, rg);

#pragma unroll 4
    for (int k = 0; k < K_IN; k += 2) {
        load_stage(B, Xsh, wrow0, wrow1, k + 1, rg);   // B loads issue first
        fma_stage(acc, A);                             // A computes (64 issue-cyc)
        if (k + 2 < K_IN)
            load_stage(A, Xsh, wrow0, wrow1, k + 2, rg);
        fma_stage(acc, B);
    }

    // epilogue: bias via __ldg (L2-hot), 2 coalesced STG.128 per row
    const float4 b0 = __ldg((const float4*)(b + c * O_OUT + 4 * cg));
    const float4 b1 = __ldg((const float4*)(b + c * O_OUT + 64 + 4 * cg));

#pragma unroll
    for (int i = 0; i < 8; ++i) {
        int n = n0 + rg + 16 * i;
        float* orow = out + ((size_t)n * C_TOT + c) * O_OUT;
        float2 p0 = unpack2(acc[i][0]);
        float2 p1 = unpack2(acc[i][1]);
        float2 p2 = unpack2(acc[i][2]);
        float2 p3 = unpack2(acc[i][3]);
        float4 v0 = make_float4(p0.x + b0.x, p0.y + b0.y, p1.x + b0.z, p1.y + b0.w);
        float4 v1 = make_float4(p2.x + b1.x, p2.y + b1.y, p3.x + b1.z, p3.y + b1.w);
        *(float4*)&orow[4 * cg]      = v0;
        *(float4*)&orow[64 + 4 * cg] = v1;
    }
}

extern "C" void kernel_launch(void* const* d_in, const int* in_sizes, int n_in,
                              void* d_out, int out_size) {
    const float* x = (const float*)d_in[0];
    const float* W = (const float*)d_in[1];
    const float* b = (const float*)d_in[2];
    float* out = (float*)d_out;

    w_transpose<<<C_TOT, 256>>>(W);

    size_t smem_bytes = (size_t)(TILE_M * XSTR + K_IN * WSTR) * sizeof(float); // 68608
    cudaFuncSetAttribute(dw1d_kernel,
                         cudaFuncAttributeMaxDynamicSharedMemorySize,
                         (int)smem_bytes);
    dim3 grid(N_TOT / TILE_M, C_TOT);
    dw1d_kernel<<<grid, THREADS, smem_bytes>>>(x, b, out);
}

// round 15
// speedup vs baseline: 1.0695x; 1.0695x over previous
#include <cuda_runtime.h>
#include <cstdint>

// Depthwise1d: out[n,c,o] = sum_i x[n,c,i] * W[c,o,i] + b[c,o]
// N=4096, C=256, K=64, O=128, fp32.
//
// FINAL (= R6 champion, 313.2us): col-pair packed FFMA2 (acc f32x2 = adjacent
// output cols), register tile r=8 rows x c=8 cols, 16 warps/SM (2 CTAs x 256
// thr). W pre-transposed to k-major by a tiny helper kernel into __device__
// scratch, so the main kernel has zero transposes:
//   x: natural Xsh[row][k], LDS.32 broadcast reads
//   W: Wsh[k][o], LDS.128 gives 2 col-pairs
//   epilogue: 2 coalesced STG.128 per row
// This tile is information-theoretically co-bound (L1 wf : fma cyc = 1:1);
// R9/R10/R11/R13 falsification attempts all measured worse.

#define N_TOT   4096
#define C_TOT   256
#define K_IN    64
#define O_OUT   128
#define TILE_M  128
#define THREADS 256
#define XSTR    68       // Xsh row stride (floats)
#define WSTR    132      // Wsh k-row stride (floats)

// 8 MB scratch: W2g[c][k][o]
__device__ float W2g[C_TOT * K_IN * O_OUT];

__device__ __forceinline__ void ffma2(unsigned long long& d,
                                      unsigned long long a,
                                      unsigned long long b) {
    asm("fma.rn.f32x2 %0, %1, %2, %0;" : "+l"(d) : "l"(a), "l"(b));
}
__device__ __forceinline__ unsigned long long dup2(float w) {
    unsigned long long r;
    asm("mov.b64 %0, {%1, %1};" : "=l"(r) : "f"(w));
    return r;
}
__device__ __forceinline__ float2 unpack2(unsigned long long v) {
    float2 f;
    asm("mov.b64 {%0, %1}, %2;" : "=f"(f.x), "=f"(f.y) : "l"(v));
    return f;
}

// ---- Kernel A: W[c][o][k] -> W2g[c][k][o] (tiny, ~7us) ----
__global__ __launch_bounds__(256)
void w_transpose(const float* __restrict__ W) {
    __shared__ float Wt[O_OUT * 68];       // [o][k] stride 68
    const int t = threadIdx.x;
    const int c = blockIdx.x;
#pragma unroll
    for (int j = 0; j < 8; ++j) {
        int idx = t + 256 * j;             // 0..2047
        int o = idx >> 4, q = idx & 15;
        float4 v = *(const float4*)(W + ((size_t)c * O_OUT + o) * K_IN + 4 * q);
        *(float4*)&Wt[o * 68 + 4 * q] = v;
    }
    __syncthreads();
    float* dst = W2g + (size_t)c * K_IN * O_OUT;
#pragma unroll
    for (int j = 0; j < 32; ++j) {
        int idx = t + 256 * j;             // 0..8191
        int k = idx >> 7, o = idx & 127;
        dst[k * O_OUT + o] = Wt[o * 68 + k];
    }
}

// ---- Kernel B: main GEMM ----
__global__ __launch_bounds__(THREADS, 2)
void dw1d_kernel(const float* __restrict__ x,
                 const float* __restrict__ b,
                 float* __restrict__ out) {
    extern __shared__ float smem[];
    float* bias_sh = smem;                       // 128 floats
    float* Xsh = smem + 128;                     // [row][k] stride 68
    float* Wsh = smem + 128 + TILE_M * XSTR;     // [k][o]  stride 132

    const int t  = threadIdx.x;
    const int cg = t & 15;
    const int rg = t >> 4;
    const int n0 = blockIdx.x * TILE_M;
    const int c  = blockIdx.y;

    if (t < O_OUT) bias_sh[t] = b[c * O_OUT + t];

    // stage x: coalesced LDG.128 -> Xsh[row][k]
    {
        const float* xb = x + (size_t)c * K_IN;
#pragma unroll
        for (int j = 0; j < 8; ++j) {
            int idx = t + THREADS * j;     // 0..2047
            int row = idx >> 4, ku = idx & 15;
            float4 v = *(const float4*)(xb + (size_t)(n0 + row) * C_TOT * K_IN + 4 * ku);
            *(float4*)&Xsh[row * XSTR + 4 * ku] = v;
        }
    }
    // stage W (already k-major): coalesced LDG.128 -> Wsh[k][o]
    {
        const float* wb = W2g + (size_t)c * K_IN * O_OUT;
#pragma unroll
        for (int j = 0; j < 8; ++j) {
            int idx = t + THREADS * j;     // 0..2047
            int k = idx >> 5, o4 = idx & 31;
            float4 v = *(const float4*)(wb + k * O_OUT + 4 * o4);
            *(float4*)&Wsh[k * WSTR + 4 * o4] = v;
        }
    }
    __syncthreads();

    // compute: rows r_i = rg + 16*i (i<8); cols 4cg..4cg+3 and 64+4cg..+3
    unsigned long long acc[8][4];
#pragma unroll
    for (int i = 0; i < 8; ++i)
#pragma unroll
        for (int j = 0; j < 4; ++j)
            acc[i][j] = 0ULL;

    const float* wrow0 = &Wsh[4 * cg];
    const float* wrow1 = &Wsh[4 * cg + 64];

#pragma unroll 4
    for (int k = 0; k < K_IN; ++k) {
        float xs[8];
#pragma unroll
        for (int i = 0; i < 8; ++i)
            xs[i] = Xsh[(rg + 16 * i) * XSTR + k];   // half-warp broadcast, 1 wf

        ulonglong2 wv0 = *(const ulonglong2*)(wrow0 + k * WSTR);
        ulonglong2 wv1 = *(const ulonglong2*)(wrow1 + k * WSTR);
#pragma unroll
        for (int i = 0; i < 8; ++i) {
            unsigned long long xd = dup2(xs[i]);
            ffma2(acc[i][0], xd, wv0.x);
            ffma2(acc[i][1], xd, wv0.y);
            ffma2(acc[i][2], xd, wv1.x);
            ffma2(acc[i][3], xd, wv1.y);
        }
    }

    // epilogue: bias + 2 coalesced STG.128 per row
    float4 b0 = *(const float4*)&bias_sh[4 * cg];
    float4 b1 = *(const float4*)&bias_sh[64 + 4 * cg];

#pragma unroll
    for (int i = 0; i < 8; ++i) {
        int n = n0 + rg + 16 * i;
        float* orow = out + ((size_t)n * C_TOT + c) * O_OUT;
        float2 p0 = unpack2(acc[i][0]);
        float2 p1 = unpack2(acc[i][1]);
        float2 p2 = unpack2(acc[i][2]);
        float2 p3 = unpack2(acc[i][3]);
        float4 v0 = make_float4(p0.x + b0.x, p0.y + b0.y, p1.x + b0.z, p1.y + b0.w);
        float4 v1 = make_float4(p2.x + b1.x, p2.y + b1.y, p3.x + b1.z, p3.y + b1.w);
        *(float4*)&orow[4 * cg]      = v0;
        *(float4*)&orow[64 + 4 * cg] = v1;
    }
}

extern "C" void kernel_launch(void* const* d_in, const int* in_sizes, int n_in,
                              void* d_out, int out_size) {
    const float* x = (const float*)d_in[0];
    const float* W = (const float*)d_in[1];
    const float* b = (const float*)d_in[2];
    float* out = (float*)d_out;

    w_transpose<<<C_TOT, 256>>>(W);

    size_t smem_bytes = (size_t)(128 + TILE_M * XSTR + K_IN * WSTR) * sizeof(float); // 69120
    cudaFuncSetAttribute(dw1d_kernel,
                         cudaFuncAttributeMaxDynamicSharedMemorySize,
                         (int)smem_bytes);
    dim3 grid(N_TOT / TILE_M, C_TOT);
    dw1d_kernel<<<grid, THREADS, smem_bytes>>>(x, b, out);
}